// round 14
// baseline (speedup 1.0000x reference)
#include <cuda_runtime.h>
#include <cuda_fp16.h>
#include <cstdint>

#define NV 100000
#define NE 800000
#define D  256

// ---------------- device scratch (allocation-free) -------------------------
__device__ __align__(16) float g_aggr[(size_t)NV * D];
__device__ int g_idx_is64;
// W^T in fp16, 16 chunks of [256 n][64 k]: 0-7 = W1 (K=512), 8-11 = W2, 12-15 = W3.
__device__ __align__(16) unsigned short g_Bhi[16][16384];
// CSR build scratch
#define SCANB 391                       /* ceil(NV/256) */
__device__ unsigned g_cnt[NV];
__device__ unsigned g_off[NV];
__device__ unsigned g_cur[NV];
__device__ int      g_eid[NE];
__device__ unsigned g_bsum[512];
__device__ unsigned g_boff[512];

// ---------------- helpers --------------------------------------------------
__device__ __forceinline__ uint32_t smem_u32(const void* p) {
    uint32_t a;
    asm("{ .reg .u64 t; cvta.to.shared.u64 t, %1; cvt.u32.u64 %0, t; }"
        : "=r"(a) : "l"(p));
    return a;
}
__device__ __forceinline__ void ldm4(unsigned* r, uint32_t addr) {
    asm volatile("ldmatrix.sync.aligned.m8n8.x4.shared.b16 {%0,%1,%2,%3}, [%4];"
                 : "=r"(r[0]), "=r"(r[1]), "=r"(r[2]), "=r"(r[3]) : "r"(addr));
}
__device__ __forceinline__ void mma16816(float* c, const unsigned* a, const unsigned* b) {
    asm volatile("mma.sync.aligned.m16n8k16.row.col.f32.f16.f16.f32 "
                 "{%0,%1,%2,%3}, {%4,%5,%6,%7}, {%8,%9}, {%0,%1,%2,%3};"
                 : "+f"(c[0]), "+f"(c[1]), "+f"(c[2]), "+f"(c[3])
                 : "r"(a[0]), "r"(a[1]), "r"(a[2]), "r"(a[3]), "r"(b[0]), "r"(b[1]));
}
__device__ __forceinline__ void cp16(uint32_t d, const void* s) {
    asm volatile("cp.async.cg.shared.global [%0], [%1], 16;"
                 :: "r"(d), "l"(s) : "memory");
}
__device__ __forceinline__ uint32_t packh2(float a, float b) {
    __half2 h = __floats2half2_rn(a, b);
    return *(uint32_t*)&h;
}

// ---------------- dtype detect ---------------------------------------------
__global__ void detect_idx_kernel(const int* __restrict__ idx_raw) {
    int is64 = 1;
#pragma unroll 1
    for (int i = 0; i < 64; i++)
        if (idx_raw[2 * i + 1] != 0) { is64 = 0; break; }
    g_idx_is64 = is64;
}
__device__ __forceinline__ int load_recv(const void* eidx_raw, int e) {
    if (g_idx_is64) return (int)((const long long*)eidx_raw)[NE + e];
    return ((const int*)eidx_raw)[NE + e];
}

// ---------------- CSR build: hist -> 3-kernel scan -> fill ------------------
__global__ void zero_cnt_kernel() {
    int i = blockIdx.x * 256 + threadIdx.x;
    if (i < NV) g_cnt[i] = 0;
}
__global__ void hist_kernel(const void* __restrict__ eidx_raw) {
    int e = blockIdx.x * 256 + threadIdx.x;          // 3125 x 256 = NE exact
    int r = load_recv(eidx_raw, e);
    if (r >= 0 && r < NV) atomicAdd(&g_cnt[r], 1u);
}
__global__ void scan1_kernel() {
    __shared__ unsigned s[256];
    int t = threadIdx.x, i = blockIdx.x * 256 + t;
    unsigned c = (i < NV) ? g_cnt[i] : 0u;
    s[t] = c;  __syncthreads();
#pragma unroll
    for (int o = 1; o < 256; o <<= 1) {
        unsigned add = (t >= o) ? s[t - o] : 0u;
        __syncthreads(); s[t] += add; __syncthreads();
    }
    if (i < NV) g_off[i] = s[t] - c;
    if (t == 255) g_bsum[blockIdx.x] = s[255];
}
__global__ void scan2_kernel() {                      // 1 block, 512 threads
    __shared__ unsigned s[512];
    int t = threadIdx.x;
    unsigned c = (t < SCANB) ? g_bsum[t] : 0u;
    s[t] = c;  __syncthreads();
#pragma unroll
    for (int o = 1; o < 512; o <<= 1) {
        unsigned add = (t >= o) ? s[t - o] : 0u;
        __syncthreads(); s[t] += add; __syncthreads();
    }
    g_boff[t] = s[t] - c;
}
__global__ void addback_kernel() {
    int i = blockIdx.x * 256 + threadIdx.x;
    if (i < NV) {
        unsigned o = g_off[i] + g_boff[blockIdx.x];
        g_off[i] = o;  g_cur[i] = o;
    }
}
__global__ void fill_kernel(const void* __restrict__ eidx_raw) {
    int e = blockIdx.x * 256 + threadIdx.x;
    int r = load_recv(eidx_raw, e);
    if (r >= 0 && r < NV) g_eid[atomicAdd(&g_cur[r], 1u)] = e;
}

// ---------------- gather-sum: one warp per vertex --------------------------
__global__ void gather_kernel(const float* __restrict__ efeat) {
    int v    = blockIdx.x * 8 + (threadIdx.x >> 5);   // 12500 x 8 = NV exact
    int lane = threadIdx.x & 31;
    unsigned start = g_off[v];
    unsigned deg   = g_cnt[v];
    float4 a0 = make_float4(0.f, 0.f, 0.f, 0.f);
    float4 a1 = make_float4(0.f, 0.f, 0.f, 0.f);
    unsigned i = 0;
    for (; i + 2 <= deg; i += 2) {
        int e0 = __ldg(&g_eid[start + i]);
        int e1 = __ldg(&g_eid[start + i + 1]);
        const float4* s0 = (const float4*)(efeat + (size_t)e0 * D);
        const float4* s1 = (const float4*)(efeat + (size_t)e1 * D);
        float4 b0 = __ldg(s0 + lane), b1 = __ldg(s0 + lane + 32);
        float4 c0 = __ldg(s1 + lane), c1 = __ldg(s1 + lane + 32);
        a0.x += b0.x; a0.y += b0.y; a0.z += b0.z; a0.w += b0.w;
        a1.x += b1.x; a1.y += b1.y; a1.z += b1.z; a1.w += b1.w;
        a0.x += c0.x; a0.y += c0.y; a0.z += c0.z; a0.w += c0.w;
        a1.x += c1.x; a1.y += c1.y; a1.z += c1.z; a1.w += c1.w;
    }
    if (i < deg) {
        int e0 = __ldg(&g_eid[start + i]);
        const float4* s0 = (const float4*)(efeat + (size_t)e0 * D);
        float4 b0 = __ldg(s0 + lane), b1 = __ldg(s0 + lane + 32);
        a0.x += b0.x; a0.y += b0.y; a0.z += b0.z; a0.w += b0.w;
        a1.x += b1.x; a1.y += b1.y; a1.z += b1.z; a1.w += b1.w;
    }
    float4* dst = (float4*)(g_aggr + (size_t)v * D);
    dst[lane]      = a0;
    dst[lane + 32] = a1;
}

// ---------------- weight prep: transpose + fp16 ----------------------------
__global__ void prep_weights_kernel(const float* __restrict__ W1,
                                    const float* __restrict__ W2,
                                    const float* __restrict__ W3) {
    int chunk = blockIdx.y;
    int t = blockIdx.x * 256 + threadIdx.x;
    int n  = t >> 6;
    int kk = t & 63;
    const float* W; int kbase;
    if (chunk < 8)       { W = W1; kbase = chunk * 64; }
    else if (chunk < 12) { W = W2; kbase = (chunk - 8) * 64; }
    else                 { W = W3; kbase = (chunk - 12) * 64; }
    float w = W[(size_t)(kbase + kk) * 256 + n];
    __half wh = __float2half_rn(w);
    g_Bhi[chunk][n * 64 + kk] = *(unsigned short*)&wh;
}

// ---------------- fp16 single-product mma.sync fused MLP -------------------
// CTA 128 rows x 256 cols, 512 threads = 16 warps (4x4), warp tile 32x64.
// A: fp16 [128][264]. B: fp16 per chunk, cp.async ring over the two k-halves
// (32 flat half-chunk stages). 2 CTAs/SM.
#define ASTRIDE 528
#define BSTRIDE 144
#define OFS_A   0
#define OFS_BHI (128 * ASTRIDE)
#define SMEM_TOTAL (OFS_BHI + 256 * BSTRIDE)   /* 104448 B */

__global__ __launch_bounds__(512, 2)
void mlp_mma_kernel(const float* __restrict__ vfeat,
                    const float* __restrict__ b1,
                    const float* __restrict__ b2,
                    const float* __restrict__ b3,
                    float* __restrict__ out)
{
    extern __shared__ char smem[];
    const uint32_t sb = smem_u32(smem);
    const int tid  = threadIdx.x;
    const int lane = tid & 31;
    const int wid  = tid >> 5;
    const int wr0  = (wid >> 2) * 32;
    const int wc0  = (wid & 3) * 64;
    const int row0 = blockIdx.x * 128;

    const uint32_t aOfs = (uint32_t)(wr0 + (lane & 15)) * ASTRIDE + ((lane >> 4) << 4);
    const uint32_t bOfs = (uint32_t)(wc0 + (lane & 7) + ((lane >> 4) << 3)) * BSTRIDE
                        + (((lane >> 3) & 1) << 4);
    const uint32_t aS  = sb + OFS_A   + aOfs;
    const uint32_t bHi = sb + OFS_BHI + bOfs;

    // B half-chunk stage: 256n x 32k fp16 = 16KB = 1024 int4; 2 per thread.
    auto issueB = [&](int g) {
        if (g >= 32) return;
        int img = (g < 16) ? (g >> 1)
                           : (g < 24) ? (8 + ((g - 16) >> 1))
                                      : (12 + ((g - 24) >> 1));
        int kh = g & 1;
        const char* sh = (const char*)g_Bhi[img];
#pragma unroll
        for (int i = 0; i < 2; i++) {
            int v = i * 512 + tid;              // 0..1023
            int n = v >> 2, q = v & 3;
            uint32_t dofs = (uint32_t)n * BSTRIDE + kh * 64 + q * 16;
            int sofs = n * 128 + kh * 64 + q * 16;
            cp16(sb + OFS_BHI + dofs, sh + sofs);
        }
        asm volatile("cp.async.commit_group;" ::: "memory");
    };

    // ---- layer-1 A register prefetch ----
    const int ar  = tid >> 2;
    const int acb = (tid & 3) * 16;
    const bool aok = (row0 + ar) < NV;
    float4 aregs[4];
    auto loadA = [&](int c) {
        const float* src = (c < 4) ? (vfeat + c * 64) : (g_aggr + (c - 4) * 64);
#pragma unroll
        for (int i = 0; i < 4; i++) {
            aregs[i] = make_float4(0.f, 0.f, 0.f, 0.f);
            if (aok) aregs[i] = *(const float4*)(src + (size_t)(row0 + ar) * D + acb + i * 4);
        }
    };
    auto writeA = [&](int c) {
        int slot = c & 3;
        char* a = smem + OFS_A + ar * ASTRIDE + (slot * 64 + acb) * 2;
#pragma unroll
        for (int i = 0; i < 4; i++)
            *(uint2*)(a + i * 8) = make_uint2(packh2(aregs[i].x, aregs[i].y),
                                              packh2(aregs[i].z, aregs[i].w));
    };

    float acc[2][8][4];
    int g = 0;

    issueB(0); issueB(1);
    loadA(0);

#pragma unroll 1
    for (int layer = 0; layer < 3; layer++) {
#pragma unroll
        for (int i = 0; i < 2; i++)
#pragma unroll
            for (int j = 0; j < 8; j++)
#pragma unroll
                for (int q = 0; q < 4; q++) acc[i][j][q] = 0.f;

        const int nchunks = (layer == 0) ? 8 : 4;
#pragma unroll 1
        for (int c = 0; c < nchunks; c++) {
            if (layer == 0) {
                writeA(c);
                if (c < 7) loadA(c + 1);
            }
#pragma unroll 1
            for (int h = 0; h < 2; h++) {
                if (g == 31) asm volatile("cp.async.wait_group 0;" ::: "memory");
                else         asm volatile("cp.async.wait_group 1;" ::: "memory");
                __syncthreads();

                const int colbase = ((layer == 0) ? (c & 3) : c) * 64;
                const int acol = colbase + h * 32;
#pragma unroll
                for (int k0 = 0; k0 < 32; k0 += 16) {
                    const uint32_t kbA = (uint32_t)(acol + k0) * 2;
                    const uint32_t kbB = (uint32_t)(h * 32 + k0) * 2;
                    unsigned a4[2][4], bh4[4][4];
                    ldm4(a4[0], aS + kbA);
                    ldm4(a4[1], aS + 16 * ASTRIDE + kbA);
#pragma unroll
                    for (int blk = 0; blk < 4; blk++)
                        ldm4(bh4[blk], bHi + blk * 16 * BSTRIDE + kbB);
#pragma unroll
                    for (int i = 0; i < 2; i++)
#pragma unroll
                        for (int j = 0; j < 8; j++)
                            mma16816(acc[i][j], a4[i], &bh4[j >> 1][(j & 1) * 2]);
                }
                __syncthreads();
                issueB(g + 2);
                g++;
            }
        }

        // ---- epilogue ----
        const float* bias = (layer == 0) ? b1 : (layer == 1) ? b2 : b3;
        const int rbase = wr0 + (lane >> 2);
        const int cbase = wc0 + (lane & 3) * 2;
        if (layer < 2) {                         // bias+ReLU -> fp16 -> A smem
#pragma unroll
            for (int i = 0; i < 2; i++)
#pragma unroll
                for (int j = 0; j < 8; j++) {
                    int col = cbase + j * 8;
                    float bb0 = bias[col], bb1 = bias[col + 1];
                    float v0 = fmaxf(acc[i][j][0] + bb0, 0.f);
                    float v1 = fmaxf(acc[i][j][1] + bb1, 0.f);
                    float v2 = fmaxf(acc[i][j][2] + bb0, 0.f);
                    float v3 = fmaxf(acc[i][j][3] + bb1, 0.f);
                    int r0 = rbase + i * 16, r1 = r0 + 8;
                    *(uint32_t*)(smem + OFS_A + r0 * ASTRIDE + col * 2) = packh2(v0, v1);
                    *(uint32_t*)(smem + OFS_A + r1 * ASTRIDE + col * 2) = packh2(v2, v3);
                }
            __syncthreads();
        } else {                                 // final: bias -> gmem
#pragma unroll
            for (int i = 0; i < 2; i++) {
                int r0 = row0 + rbase + i * 16;
#pragma unroll
                for (int j = 0; j < 8; j++) {
                    int col = cbase + j * 8;
                    float bb0 = bias[col], bb1 = bias[col + 1];
                    if (r0 < NV) {
                        float2 v = make_float2(acc[i][j][0] + bb0, acc[i][j][1] + bb1);
                        *(float2*)(out + (size_t)r0 * D + col) = v;
                    }
                    if (r0 + 8 < NV) {
                        float2 v = make_float2(acc[i][j][2] + bb0, acc[i][j][3] + bb1);
                        *(float2*)(out + (size_t)(r0 + 8) * D + col) = v;
                    }
                }
            }
        }
    }
}

// ---------------------------------------------------------------------------
extern "C" void kernel_launch(void* const* d_in, const int* in_sizes, int n_in,
                              void* d_out, int out_size) {
    const float* vfeat = (const float*)d_in[0];
    const float* efeat = (const float*)d_in[1];
    const void*  eidx  = d_in[2];                 // [2, NE] int64 OR int32
    const float* W1 = (const float*)d_in[3];
    const float* b1 = (const float*)d_in[4];
    const float* W2 = (const float*)d_in[5];
    const float* b2 = (const float*)d_in[6];
    const float* W3 = (const float*)d_in[7];
    const float* b3 = (const float*)d_in[8];
    float* out = (float*)d_out;

    cudaFuncSetAttribute(mlp_mma_kernel,
                         cudaFuncAttributeMaxDynamicSharedMemorySize, SMEM_TOTAL);

    detect_idx_kernel<<<1, 1>>>((const int*)eidx);
    zero_cnt_kernel<<<SCANB, 256>>>();
    hist_kernel<<<NE / 256, 256>>>(eidx);
    scan1_kernel<<<SCANB, 256>>>();
    scan2_kernel<<<1, 512>>>();
    addback_kernel<<<SCANB, 256>>>();
    fill_kernel<<<NE / 256, 256>>>(eidx);
    gather_kernel<<<NV / 8, 256>>>(efeat);
    prep_weights_kernel<<<dim3(64, 16), 256>>>(W1, W2, W3);
    mlp_mma_kernel<<<(NV + 127) / 128, 512, SMEM_TOTAL>>>(vfeat, b1, b2, b3, out);
}

// round 16
// speedup vs baseline: 2.0193x; 2.0193x over previous
#include <cuda_runtime.h>
#include <cuda_fp16.h>
#include <cstdint>

#define NV 100000
#define NE 800000
#define D  256

// ---------------- device scratch (allocation-free) -------------------------
__device__ __align__(16) float g_aggr[(size_t)NV * D];
__device__ int g_idx_is64;
// W^T in fp16, 16 chunks of [256 n][64 k]: 0-7 = W1 (K=512), 8-11 = W2, 12-15 = W3.
__device__ __align__(16) unsigned short g_Bhi[16][16384];
// CSR build scratch
#define SCANB 391                       /* ceil(NV/256) */
__device__ unsigned g_cnt[NV];
__device__ unsigned g_off[NV];
__device__ unsigned g_cur[NV];
__device__ int      g_eid[NE];
__device__ unsigned g_bsum[512];
__device__ unsigned g_boff[512];

// ---------------- helpers --------------------------------------------------
__device__ __forceinline__ uint32_t smem_u32(const void* p) {
    uint32_t a;
    asm("{ .reg .u64 t; cvta.to.shared.u64 t, %1; cvt.u32.u64 %0, t; }"
        : "=r"(a) : "l"(p));
    return a;
}
__device__ __forceinline__ void ldm4(unsigned* r, uint32_t addr) {
    asm volatile("ldmatrix.sync.aligned.m8n8.x4.shared.b16 {%0,%1,%2,%3}, [%4];"
                 : "=r"(r[0]), "=r"(r[1]), "=r"(r[2]), "=r"(r[3]) : "r"(addr));
}
__device__ __forceinline__ void mma16816(float* c, const unsigned* a, const unsigned* b) {
    asm volatile("mma.sync.aligned.m16n8k16.row.col.f32.f16.f16.f32 "
                 "{%0,%1,%2,%3}, {%4,%5,%6,%7}, {%8,%9}, {%0,%1,%2,%3};"
                 : "+f"(c[0]), "+f"(c[1]), "+f"(c[2]), "+f"(c[3])
                 : "r"(a[0]), "r"(a[1]), "r"(a[2]), "r"(a[3]), "r"(b[0]), "r"(b[1]));
}
__device__ __forceinline__ void cp16(uint32_t d, const void* s) {
    asm volatile("cp.async.cg.shared.global [%0], [%1], 16;"
                 :: "r"(d), "l"(s) : "memory");
}
__device__ __forceinline__ uint32_t packh2(float a, float b) {
    __half2 h = __floats2half2_rn(a, b);
    return *(uint32_t*)&h;
}

// ---------------- dtype detect ---------------------------------------------
__global__ void detect_idx_kernel(const int* __restrict__ idx_raw) {
    int is64 = 1;
#pragma unroll 1
    for (int i = 0; i < 64; i++)
        if (idx_raw[2 * i + 1] != 0) { is64 = 0; break; }
    g_idx_is64 = is64;
}
__device__ __forceinline__ int load_recv(const void* eidx_raw, int e) {
    if (g_idx_is64) return (int)((const long long*)eidx_raw)[NE + e];
    return ((const int*)eidx_raw)[NE + e];
}

// ---------------- CSR build: hist -> 3-kernel scan -> fill ------------------
__global__ void zero_cnt_kernel() {
    int i = blockIdx.x * 256 + threadIdx.x;
    if (i < NV) g_cnt[i] = 0;
}
__global__ void hist_kernel(const void* __restrict__ eidx_raw) {
    int e = blockIdx.x * 256 + threadIdx.x;          // 3125 x 256 = NE exact
    int r = load_recv(eidx_raw, e);
    if (r >= 0 && r < NV) atomicAdd(&g_cnt[r], 1u);
}
__global__ void scan1_kernel() {
    __shared__ unsigned s[256];
    int t = threadIdx.x, i = blockIdx.x * 256 + t;
    unsigned c = (i < NV) ? g_cnt[i] : 0u;
    s[t] = c;  __syncthreads();
#pragma unroll
    for (int o = 1; o < 256; o <<= 1) {
        unsigned add = (t >= o) ? s[t - o] : 0u;
        __syncthreads(); s[t] += add; __syncthreads();
    }
    if (i < NV) g_off[i] = s[t] - c;
    if (t == 255) g_bsum[blockIdx.x] = s[255];
}
__global__ void scan2_kernel() {                      // 1 block, 512 threads
    __shared__ unsigned s[512];
    int t = threadIdx.x;
    unsigned c = (t < SCANB) ? g_bsum[t] : 0u;
    s[t] = c;  __syncthreads();
#pragma unroll
    for (int o = 1; o < 512; o <<= 1) {
        unsigned add = (t >= o) ? s[t - o] : 0u;
        __syncthreads(); s[t] += add; __syncthreads();
    }
    g_boff[t] = s[t] - c;
}
__global__ void addback_kernel() {
    int i = blockIdx.x * 256 + threadIdx.x;
    if (i < NV) {
        unsigned o = g_off[i] + g_boff[blockIdx.x];
        g_off[i] = o;  g_cur[i] = o;
    }
}
__global__ void fill_kernel(const void* __restrict__ eidx_raw) {
    int e = blockIdx.x * 256 + threadIdx.x;
    int r = load_recv(eidx_raw, e);
    if (r >= 0 && r < NV) g_eid[atomicAdd(&g_cur[r], 1u)] = e;
}

// ---------------- gather-sum: one warp per vertex --------------------------
__global__ void gather_kernel(const float* __restrict__ efeat) {
    int v    = blockIdx.x * 8 + (threadIdx.x >> 5);   // 12500 x 8 = NV exact
    int lane = threadIdx.x & 31;
    unsigned start = g_off[v];
    unsigned deg   = g_cnt[v];
    float4 a0 = make_float4(0.f, 0.f, 0.f, 0.f);
    float4 a1 = make_float4(0.f, 0.f, 0.f, 0.f);
    unsigned i = 0;
    for (; i + 2 <= deg; i += 2) {
        int e0 = __ldg(&g_eid[start + i]);
        int e1 = __ldg(&g_eid[start + i + 1]);
        const float4* s0 = (const float4*)(efeat + (size_t)e0 * D);
        const float4* s1 = (const float4*)(efeat + (size_t)e1 * D);
        float4 b0 = __ldg(s0 + lane), b1 = __ldg(s0 + lane + 32);
        float4 c0 = __ldg(s1 + lane), c1 = __ldg(s1 + lane + 32);
        a0.x += b0.x; a0.y += b0.y; a0.z += b0.z; a0.w += b0.w;
        a1.x += b1.x; a1.y += b1.y; a1.z += b1.z; a1.w += b1.w;
        a0.x += c0.x; a0.y += c0.y; a0.z += c0.z; a0.w += c0.w;
        a1.x += c1.x; a1.y += c1.y; a1.z += c1.z; a1.w += c1.w;
    }
    if (i < deg) {
        int e0 = __ldg(&g_eid[start + i]);
        const float4* s0 = (const float4*)(efeat + (size_t)e0 * D);
        float4 b0 = __ldg(s0 + lane), b1 = __ldg(s0 + lane + 32);
        a0.x += b0.x; a0.y += b0.y; a0.z += b0.z; a0.w += b0.w;
        a1.x += b1.x; a1.y += b1.y; a1.z += b1.z; a1.w += b1.w;
    }
    float4* dst = (float4*)(g_aggr + (size_t)v * D);
    dst[lane]      = a0;
    dst[lane + 32] = a1;
}

// ---------------- weight prep: transpose + fp16 ----------------------------
__global__ void prep_weights_kernel(const float* __restrict__ W1,
                                    const float* __restrict__ W2,
                                    const float* __restrict__ W3) {
    int chunk = blockIdx.y;
    int t = blockIdx.x * 256 + threadIdx.x;
    int n  = t >> 6;
    int kk = t & 63;
    const float* W; int kbase;
    if (chunk < 8)       { W = W1; kbase = chunk * 64; }
    else if (chunk < 12) { W = W2; kbase = (chunk - 8) * 64; }
    else                 { W = W3; kbase = (chunk - 12) * 64; }
    float w = W[(size_t)(kbase + kk) * 256 + n];
    __half wh = __float2half_rn(w);
    g_Bhi[chunk][n * 64 + kk] = *(unsigned short*)&wh;
}

// ---------------- fp16 single-product mma.sync fused MLP -------------------
// CTA 128 rows x 256 cols, 512 threads = 16 warps (4x4), warp tile 32x64.
// A: fp16 [128][264]. B: fp16 per chunk, cp.async ring over the two k-halves
// (32 flat half-chunk stages). 1 CTA/SM: full 128-reg budget, no spills.
#define ASTRIDE 528
#define BSTRIDE 144
#define OFS_A   0
#define OFS_BHI (128 * ASTRIDE)
#define SMEM_TOTAL (OFS_BHI + 256 * BSTRIDE)   /* 104448 B */

__global__ __launch_bounds__(512, 1)
void mlp_mma_kernel(const float* __restrict__ vfeat,
                    const float* __restrict__ b1,
                    const float* __restrict__ b2,
                    const float* __restrict__ b3,
                    float* __restrict__ out)
{
    extern __shared__ char smem[];
    const uint32_t sb = smem_u32(smem);
    const int tid  = threadIdx.x;
    const int lane = tid & 31;
    const int wid  = tid >> 5;
    const int wr0  = (wid >> 2) * 32;
    const int wc0  = (wid & 3) * 64;
    const int row0 = blockIdx.x * 128;

    const uint32_t aOfs = (uint32_t)(wr0 + (lane & 15)) * ASTRIDE + ((lane >> 4) << 4);
    const uint32_t bOfs = (uint32_t)(wc0 + (lane & 7) + ((lane >> 4) << 3)) * BSTRIDE
                        + (((lane >> 3) & 1) << 4);
    const uint32_t aS  = sb + OFS_A   + aOfs;
    const uint32_t bHi = sb + OFS_BHI + bOfs;

    // B half-chunk stage: 256n x 32k fp16 = 16KB = 1024 int4; 2 per thread.
    auto issueB = [&](int g) {
        if (g >= 32) return;
        int img = (g < 16) ? (g >> 1)
                           : (g < 24) ? (8 + ((g - 16) >> 1))
                                      : (12 + ((g - 24) >> 1));
        int kh = g & 1;
        const char* sh = (const char*)g_Bhi[img];
#pragma unroll
        for (int i = 0; i < 2; i++) {
            int v = i * 512 + tid;              // 0..1023
            int n = v >> 2, q = v & 3;
            uint32_t dofs = (uint32_t)n * BSTRIDE + kh * 64 + q * 16;
            int sofs = n * 128 + kh * 64 + q * 16;
            cp16(sb + OFS_BHI + dofs, sh + sofs);
        }
        asm volatile("cp.async.commit_group;" ::: "memory");
    };

    // ---- layer-1 A register prefetch ----
    const int ar  = tid >> 2;
    const int acb = (tid & 3) * 16;
    const bool aok = (row0 + ar) < NV;
    float4 aregs[4];
    auto loadA = [&](int c) {
        const float* src = (c < 4) ? (vfeat + c * 64) : (g_aggr + (c - 4) * 64);
#pragma unroll
        for (int i = 0; i < 4; i++) {
            aregs[i] = make_float4(0.f, 0.f, 0.f, 0.f);
            if (aok) aregs[i] = *(const float4*)(src + (size_t)(row0 + ar) * D + acb + i * 4);
        }
    };
    auto writeA = [&](int c) {
        int slot = c & 3;
        char* a = smem + OFS_A + ar * ASTRIDE + (slot * 64 + acb) * 2;
#pragma unroll
        for (int i = 0; i < 4; i++)
            *(uint2*)(a + i * 8) = make_uint2(packh2(aregs[i].x, aregs[i].y),
                                              packh2(aregs[i].z, aregs[i].w));
    };

    float acc[2][8][4];
    int g = 0;

    issueB(0); issueB(1);
    loadA(0);

#pragma unroll 1
    for (int layer = 0; layer < 3; layer++) {
#pragma unroll
        for (int i = 0; i < 2; i++)
#pragma unroll
            for (int j = 0; j < 8; j++)
#pragma unroll
                for (int q = 0; q < 4; q++) acc[i][j][q] = 0.f;

        const int nchunks = (layer == 0) ? 8 : 4;
#pragma unroll 1
        for (int c = 0; c < nchunks; c++) {
            if (layer == 0) {
                writeA(c);
                if (c < 7) loadA(c + 1);
            }
#pragma unroll 1
            for (int h = 0; h < 2; h++) {
                if (g == 31) asm volatile("cp.async.wait_group 0;" ::: "memory");
                else         asm volatile("cp.async.wait_group 1;" ::: "memory");
                __syncthreads();

                const int colbase = ((layer == 0) ? (c & 3) : c) * 64;
                const int acol = colbase + h * 32;
#pragma unroll
                for (int k0 = 0; k0 < 32; k0 += 16) {
                    const uint32_t kbA = (uint32_t)(acol + k0) * 2;
                    const uint32_t kbB = (uint32_t)(h * 32 + k0) * 2;
                    unsigned a4[2][4], bh4[4][4];
                    ldm4(a4[0], aS + kbA);
                    ldm4(a4[1], aS + 16 * ASTRIDE + kbA);
#pragma unroll
                    for (int blk = 0; blk < 4; blk++)
                        ldm4(bh4[blk], bHi + blk * 16 * BSTRIDE + kbB);
#pragma unroll
                    for (int i = 0; i < 2; i++)
#pragma unroll
                        for (int j = 0; j < 8; j++)
                            mma16816(acc[i][j], a4[i], &bh4[j >> 1][(j & 1) * 2]);
                }
                __syncthreads();
                issueB(g + 2);
                g++;
            }
        }

        // ---- epilogue ----
        const float* bias = (layer == 0) ? b1 : (layer == 1) ? b2 : b3;
        const int rbase = wr0 + (lane >> 2);
        const int cbase = wc0 + (lane & 3) * 2;
        if (layer < 2) {                         // bias+ReLU -> fp16 -> A smem
#pragma unroll
            for (int i = 0; i < 2; i++)
#pragma unroll
                for (int j = 0; j < 8; j++) {
                    int col = cbase + j * 8;
                    float bb0 = bias[col], bb1 = bias[col + 1];
                    float v0 = fmaxf(acc[i][j][0] + bb0, 0.f);
                    float v1 = fmaxf(acc[i][j][1] + bb1, 0.f);
                    float v2 = fmaxf(acc[i][j][2] + bb0, 0.f);
                    float v3 = fmaxf(acc[i][j][3] + bb1, 0.f);
                    int r0 = rbase + i * 16, r1 = r0 + 8;
                    *(uint32_t*)(smem + OFS_A + r0 * ASTRIDE + col * 2) = packh2(v0, v1);
                    *(uint32_t*)(smem + OFS_A + r1 * ASTRIDE + col * 2) = packh2(v2, v3);
                }
            __syncthreads();
        } else {                                 // final: bias -> gmem
#pragma unroll
            for (int i = 0; i < 2; i++) {
                int r0 = row0 + rbase + i * 16;
#pragma unroll
                for (int j = 0; j < 8; j++) {
                    int col = cbase + j * 8;
                    float bb0 = bias[col], bb1 = bias[col + 1];
                    if (r0 < NV) {
                        float2 v = make_float2(acc[i][j][0] + bb0, acc[i][j][1] + bb1);
                        *(float2*)(out + (size_t)r0 * D + col) = v;
                    }
                    if (r0 + 8 < NV) {
                        float2 v = make_float2(acc[i][j][2] + bb0, acc[i][j][3] + bb1);
                        *(float2*)(out + (size_t)(r0 + 8) * D + col) = v;
                    }
                }
            }
        }
    }
}

// ---------------------------------------------------------------------------
extern "C" void kernel_launch(void* const* d_in, const int* in_sizes, int n_in,
                              void* d_out, int out_size) {
    const float* vfeat = (const float*)d_in[0];
    const float* efeat = (const float*)d_in[1];
    const void*  eidx  = d_in[2];                 // [2, NE] int64 OR int32
    const float* W1 = (const float*)d_in[3];
    const float* b1 = (const float*)d_in[4];
    const float* W2 = (const float*)d_in[5];
    const float* b2 = (const float*)d_in[6];
    const float* W3 = (const float*)d_in[7];
    const float* b3 = (const float*)d_in[8];
    float* out = (float*)d_out;

    cudaFuncSetAttribute(mlp_mma_kernel,
                         cudaFuncAttributeMaxDynamicSharedMemorySize, SMEM_TOTAL);

    detect_idx_kernel<<<1, 1>>>((const int*)eidx);
    zero_cnt_kernel<<<SCANB, 256>>>();
    hist_kernel<<<NE / 256, 256>>>(eidx);
    scan1_kernel<<<SCANB, 256>>>();
    scan2_kernel<<<1, 512>>>();
    addback_kernel<<<SCANB, 256>>>();
    fill_kernel<<<NE / 256, 256>>>(eidx);
    gather_kernel<<<NV / 8, 256>>>(efeat);
    prep_weights_kernel<<<dim3(64, 16), 256>>>(W1, W2, W3);
    mlp_mma_kernel<<<(NV + 127) / 128, 512, SMEM_TOTAL>>>(vfeat, b1, b2, b3, out);
}

// round 17
// speedup vs baseline: 2.0352x; 1.0079x over previous
#include <cuda_runtime.h>
#include <cuda_fp16.h>
#include <cstdint>

#define NV 100000
#define NE 800000
#define D  256

// ---------------- device scratch (allocation-free) -------------------------
__device__ __align__(16) float g_aggr[(size_t)NV * D];
__device__ int g_idx_is64;
// W^T in fp16, 16 chunks of [256 n][64 k]: 0-7 = W1 (K=512), 8-11 = W2, 12-15 = W3.
__device__ __align__(16) unsigned short g_Bhi[16][16384];
// CSR build scratch
#define SCANB 391                       /* ceil(NV/256) */
__device__ unsigned g_cnt[NV];
__device__ unsigned g_off[NV];
__device__ unsigned g_cur[NV];
__device__ int      g_eid[NE];
__device__ unsigned g_bsum[512];
__device__ unsigned g_boff[512];

// ---------------- helpers --------------------------------------------------
__device__ __forceinline__ uint32_t smem_u32(const void* p) {
    uint32_t a;
    asm("{ .reg .u64 t; cvta.to.shared.u64 t, %1; cvt.u32.u64 %0, t; }"
        : "=r"(a) : "l"(p));
    return a;
}
__device__ __forceinline__ void ldm4(unsigned* r, uint32_t addr) {
    asm volatile("ldmatrix.sync.aligned.m8n8.x4.shared.b16 {%0,%1,%2,%3}, [%4];"
                 : "=r"(r[0]), "=r"(r[1]), "=r"(r[2]), "=r"(r[3]) : "r"(addr));
}
__device__ __forceinline__ void mma16816(float* c, const unsigned* a, const unsigned* b) {
    asm volatile("mma.sync.aligned.m16n8k16.row.col.f32.f16.f16.f32 "
                 "{%0,%1,%2,%3}, {%4,%5,%6,%7}, {%8,%9}, {%0,%1,%2,%3};"
                 : "+f"(c[0]), "+f"(c[1]), "+f"(c[2]), "+f"(c[3])
                 : "r"(a[0]), "r"(a[1]), "r"(a[2]), "r"(a[3]), "r"(b[0]), "r"(b[1]));
}
__device__ __forceinline__ void cp16(uint32_t d, const void* s) {
    asm volatile("cp.async.cg.shared.global [%0], [%1], 16;"
                 :: "r"(d), "l"(s) : "memory");
}
__device__ __forceinline__ uint32_t packh2(float a, float b) {
    __half2 h = __floats2half2_rn(a, b);
    return *(uint32_t*)&h;
}
__device__ __forceinline__ void add4(float4& a, const float4& b) {
    a.x += b.x; a.y += b.y; a.z += b.z; a.w += b.w;
}

// ---------------- dtype detect (folded into zero_cnt) ----------------------
__device__ __forceinline__ int load_recv(const void* eidx_raw, int e) {
    if (g_idx_is64) return (int)((const long long*)eidx_raw)[NE + e];
    return ((const int*)eidx_raw)[NE + e];
}

// ---------------- CSR build: zero+detect -> hist -> scan -> fill ------------
__global__ void zero_cnt_kernel(const int* __restrict__ idx_raw) {
    if (blockIdx.x == 0 && threadIdx.x == 0) {
        int is64 = 1;
#pragma unroll 1
        for (int i = 0; i < 64; i++)
            if (idx_raw[2 * i + 1] != 0) { is64 = 0; break; }
        g_idx_is64 = is64;
    }
    int i = blockIdx.x * 256 + threadIdx.x;
    if (i < NV) g_cnt[i] = 0;
}
__global__ void hist_kernel(const void* __restrict__ eidx_raw) {
    int e = blockIdx.x * 256 + threadIdx.x;          // 3125 x 256 = NE exact
    int r = load_recv(eidx_raw, e);
    if (r >= 0 && r < NV) atomicAdd(&g_cnt[r], 1u);
}
__global__ void scan1_kernel() {
    __shared__ unsigned s[256];
    int t = threadIdx.x, i = blockIdx.x * 256 + t;
    unsigned c = (i < NV) ? g_cnt[i] : 0u;
    s[t] = c;  __syncthreads();
#pragma unroll
    for (int o = 1; o < 256; o <<= 1) {
        unsigned add = (t >= o) ? s[t - o] : 0u;
        __syncthreads(); s[t] += add; __syncthreads();
    }
    if (i < NV) g_off[i] = s[t] - c;
    if (t == 255) g_bsum[blockIdx.x] = s[255];
}
__global__ void scan2_kernel() {                      // 1 block, 512 threads
    __shared__ unsigned s[512];
    int t = threadIdx.x;
    unsigned c = (t < SCANB) ? g_bsum[t] : 0u;
    s[t] = c;  __syncthreads();
#pragma unroll
    for (int o = 1; o < 512; o <<= 1) {
        unsigned add = (t >= o) ? s[t - o] : 0u;
        __syncthreads(); s[t] += add; __syncthreads();
    }
    g_boff[t] = s[t] - c;
}
__global__ void addback_kernel() {
    int i = blockIdx.x * 256 + threadIdx.x;
    if (i < NV) {
        unsigned o = g_off[i] + g_boff[blockIdx.x];
        g_off[i] = o;  g_cur[i] = o;
    }
}
__global__ void fill_kernel(const void* __restrict__ eidx_raw) {
    int e = blockIdx.x * 256 + threadIdx.x;
    int r = load_recv(eidx_raw, e);
    if (r >= 0 && r < NV) g_eid[atomicAdd(&g_cur[r], 1u)] = e;
}

// ---------------- gather-sum: one warp per vertex, 4-edge unroll -----------
__global__ void gather_kernel(const float* __restrict__ efeat) {
    int v    = blockIdx.x * 8 + (threadIdx.x >> 5);   // 12500 x 8 = NV exact
    int lane = threadIdx.x & 31;
    unsigned start = g_off[v];
    unsigned deg   = g_cnt[v];
    float4 a0 = make_float4(0.f, 0.f, 0.f, 0.f);
    float4 a1 = make_float4(0.f, 0.f, 0.f, 0.f);
    unsigned i = 0;
    for (; i + 4 <= deg; i += 4) {                    // 8 float4 in flight/lane
        int e0 = __ldg(&g_eid[start + i]);
        int e1 = __ldg(&g_eid[start + i + 1]);
        int e2 = __ldg(&g_eid[start + i + 2]);
        int e3 = __ldg(&g_eid[start + i + 3]);
        const float4* s0 = (const float4*)(efeat + (size_t)e0 * D);
        const float4* s1 = (const float4*)(efeat + (size_t)e1 * D);
        const float4* s2 = (const float4*)(efeat + (size_t)e2 * D);
        const float4* s3 = (const float4*)(efeat + (size_t)e3 * D);
        float4 b0 = __ldg(s0 + lane), b1 = __ldg(s0 + lane + 32);
        float4 c0 = __ldg(s1 + lane), c1 = __ldg(s1 + lane + 32);
        float4 d0 = __ldg(s2 + lane), d1 = __ldg(s2 + lane + 32);
        float4 f0 = __ldg(s3 + lane), f1 = __ldg(s3 + lane + 32);
        add4(a0, b0); add4(a1, b1);
        add4(a0, c0); add4(a1, c1);
        add4(a0, d0); add4(a1, d1);
        add4(a0, f0); add4(a1, f1);
    }
    for (; i < deg; i++) {
        int e0 = __ldg(&g_eid[start + i]);
        const float4* s0 = (const float4*)(efeat + (size_t)e0 * D);
        float4 b0 = __ldg(s0 + lane), b1 = __ldg(s0 + lane + 32);
        add4(a0, b0); add4(a1, b1);
    }
    float4* dst = (float4*)(g_aggr + (size_t)v * D);
    dst[lane]      = a0;
    dst[lane + 32] = a1;
}

// ---------------- weight prep: transpose + fp16 ----------------------------
__global__ void prep_weights_kernel(const float* __restrict__ W1,
                                    const float* __restrict__ W2,
                                    const float* __restrict__ W3) {
    int chunk = blockIdx.y;
    int t = blockIdx.x * 256 + threadIdx.x;
    int n  = t >> 6;
    int kk = t & 63;
    const float* W; int kbase;
    if (chunk < 8)       { W = W1; kbase = chunk * 64; }
    else if (chunk < 12) { W = W2; kbase = (chunk - 8) * 64; }
    else                 { W = W3; kbase = (chunk - 12) * 64; }
    float w = W[(size_t)(kbase + kk) * 256 + n];
    __half wh = __float2half_rn(w);
    g_Bhi[chunk][n * 64 + kk] = *(unsigned short*)&wh;
}

// ---------------- fp16 single-product mma.sync fused MLP -------------------
// CTA 128 rows x 256 cols, 512 threads = 16 warps (4x4), warp tile 32x64.
// A: fp16 [128][264]. B: 4-slot cp.async ring, one slot = 256n x 32k fp16
// (stride 80 B: 16B-aligned, 20 banks -> conflict-free ldmatrix phases).
// 32 flat half-chunk stages; ONE __syncthreads per stage.
#define ASTRIDE 528
#define BSTRIDE 80
#define BSLOT   (256 * BSTRIDE)        /* 20480 B */
#define OFS_A   0
#define OFS_B   (128 * ASTRIDE)        /* 67584 */
#define SMEM_TOTAL (OFS_B + 4 * BSLOT) /* 149504 B */

__global__ __launch_bounds__(512, 1)
void mlp_mma_kernel(const float* __restrict__ vfeat,
                    const float* __restrict__ b1,
                    const float* __restrict__ b2,
                    const float* __restrict__ b3,
                    float* __restrict__ out)
{
    extern __shared__ char smem[];
    const uint32_t sb = smem_u32(smem);
    const int tid  = threadIdx.x;
    const int lane = tid & 31;
    const int wid  = tid >> 5;
    const int wr0  = (wid >> 2) * 32;
    const int wc0  = (wid & 3) * 64;
    const int row0 = blockIdx.x * 128;

    const uint32_t aOfs = (uint32_t)(wr0 + (lane & 15)) * ASTRIDE + ((lane >> 4) << 4);
    const uint32_t bOfs = (uint32_t)(wc0 + (lane & 7) + ((lane >> 4) << 3)) * BSTRIDE
                        + (((lane >> 3) & 1) << 4);
    const uint32_t aS = sb + OFS_A + aOfs;

    // B half-chunk stage -> ring slot g&3: 16KB = 1024 int4; 2 per thread.
    auto issueB = [&](int g) {
        if (g < 32) {
            int img = (g < 16) ? (g >> 1)
                               : (g < 24) ? (8 + ((g - 16) >> 1))
                                          : (12 + ((g - 24) >> 1));
            int kh = g & 1;
            uint32_t slotb = sb + OFS_B + (uint32_t)(g & 3) * BSLOT;
            const char* sh = (const char*)g_Bhi[img];
#pragma unroll
            for (int i = 0; i < 2; i++) {
                int v = i * 512 + tid;              // 0..1023
                int n = v >> 2, q = v & 3;
                cp16(slotb + (uint32_t)n * BSTRIDE + q * 16,
                     sh + n * 128 + kh * 64 + q * 16);
            }
        }
        asm volatile("cp.async.commit_group;" ::: "memory");
    };

    // ---- layer-1 A register prefetch ----
    const int ar  = tid >> 2;
    const int acb = (tid & 3) * 16;
    const bool aok = (row0 + ar) < NV;
    float4 aregs[4];
    auto loadA = [&](int c) {
        const float* src = (c < 4) ? (vfeat + c * 64) : (g_aggr + (c - 4) * 64);
#pragma unroll
        for (int i = 0; i < 4; i++) {
            aregs[i] = make_float4(0.f, 0.f, 0.f, 0.f);
            if (aok) aregs[i] = *(const float4*)(src + (size_t)(row0 + ar) * D + acb + i * 4);
        }
    };
    auto writeA = [&](int c) {
        int slot = c & 3;
        char* a = smem + OFS_A + ar * ASTRIDE + (slot * 64 + acb) * 2;
#pragma unroll
        for (int i = 0; i < 4; i++)
            *(uint2*)(a + i * 8) = make_uint2(packh2(aregs[i].x, aregs[i].y),
                                              packh2(aregs[i].z, aregs[i].w));
    };

    float acc[2][8][4];
    int g = 0;

    issueB(0); issueB(1); issueB(2);
    loadA(0);

#pragma unroll 1
    for (int layer = 0; layer < 3; layer++) {
#pragma unroll
        for (int i = 0; i < 2; i++)
#pragma unroll
            for (int j = 0; j < 8; j++)
#pragma unroll
                for (int q = 0; q < 4; q++) acc[i][j][q] = 0.f;

        const int nchunks = (layer == 0) ? 8 : 4;
#pragma unroll 1
        for (int c = 0; c < nchunks; c++) {
            if (layer == 0) {
                writeA(c);
                if (c < 7) loadA(c + 1);
            }
#pragma unroll 1
            for (int h = 0; h < 2; h++) {
                // group g must be complete before compute
                if (g <= 29)      asm volatile("cp.async.wait_group 2;" ::: "memory");
                else if (g == 30) asm volatile("cp.async.wait_group 1;" ::: "memory");
                else              asm volatile("cp.async.wait_group 0;" ::: "memory");
                __syncthreads();              // stage-g data + prev-stage reads done
                issueB(g + 3);                // refill slot (g-1)&3 (safe after sync)

                const uint32_t bBase = sb + OFS_B + (uint32_t)(g & 3) * BSLOT + bOfs;
                const int colbase = ((layer == 0) ? (c & 3) : c) * 64;
                const int acol = colbase + h * 32;
#pragma unroll
                for (int k0 = 0; k0 < 32; k0 += 16) {
                    const uint32_t kbA = (uint32_t)(acol + k0) * 2;
                    const uint32_t kbB = (uint32_t)k0 * 2;
                    unsigned a4[2][4], bh4[4][4];
                    ldm4(a4[0], aS + kbA);
                    ldm4(a4[1], aS + 16 * ASTRIDE + kbA);
#pragma unroll
                    for (int blk = 0; blk < 4; blk++)
                        ldm4(bh4[blk], bBase + blk * 16 * BSTRIDE + kbB);
#pragma unroll
                    for (int i = 0; i < 2; i++)
#pragma unroll
                        for (int j = 0; j < 8; j++)
                            mma16816(acc[i][j], a4[i], &bh4[j >> 1][(j & 1) * 2]);
                }
                g++;
            }
        }
        __syncthreads();                      // all warps done with this layer's A

        // ---- epilogue (next layer's B stages already in flight) ----
        const float* bias = (layer == 0) ? b1 : (layer == 1) ? b2 : b3;
        const int rbase = wr0 + (lane >> 2);
        const int cbase = wc0 + (lane & 3) * 2;
        if (layer < 2) {                      // bias+ReLU -> fp16 -> A smem
#pragma unroll
            for (int i = 0; i < 2; i++)
#pragma unroll
                for (int j = 0; j < 8; j++) {
                    int col = cbase + j * 8;
                    float bb0 = bias[col], bb1 = bias[col + 1];
                    float v0 = fmaxf(acc[i][j][0] + bb0, 0.f);
                    float v1 = fmaxf(acc[i][j][1] + bb1, 0.f);
                    float v2 = fmaxf(acc[i][j][2] + bb0, 0.f);
                    float v3 = fmaxf(acc[i][j][3] + bb1, 0.f);
                    int r0 = rbase + i * 16, r1 = r0 + 8;
                    *(uint32_t*)(smem + OFS_A + r0 * ASTRIDE + col * 2) = packh2(v0, v1);
                    *(uint32_t*)(smem + OFS_A + r1 * ASTRIDE + col * 2) = packh2(v2, v3);
                }
            __syncthreads();                  // activations visible to all warps
        } else {                              // final: bias -> gmem
#pragma unroll
            for (int i = 0; i < 2; i++) {
                int r0 = row0 + rbase + i * 16;
#pragma unroll
                for (int j = 0; j < 8; j++) {
                    int col = cbase + j * 8;
                    float bb0 = bias[col], bb1 = bias[col + 1];
                    if (r0 < NV) {
                        float2 v = make_float2(acc[i][j][0] + bb0, acc[i][j][1] + bb1);
                        *(float2*)(out + (size_t)r0 * D + col) = v;
                    }
                    if (r0 + 8 < NV) {
                        float2 v = make_float2(acc[i][j][2] + bb0, acc[i][j][3] + bb1);
                        *(float2*)(out + (size_t)(r0 + 8) * D + col) = v;
                    }
                }
            }
        }
    }
}

// ---------------------------------------------------------------------------
extern "C" void kernel_launch(void* const* d_in, const int* in_sizes, int n_in,
                              void* d_out, int out_size) {
    const float* vfeat = (const float*)d_in[0];
    const float* efeat = (const float*)d_in[1];
    const void*  eidx  = d_in[2];                 // [2, NE] int64 OR int32
    const float* W1 = (const float*)d_in[3];
    const float* b1 = (const float*)d_in[4];
    const float* W2 = (const float*)d_in[5];
    const float* b2 = (const float*)d_in[6];
    const float* W3 = (const float*)d_in[7];
    const float* b3 = (const float*)d_in[8];
    float* out = (float*)d_out;

    cudaFuncSetAttribute(mlp_mma_kernel,
                         cudaFuncAttributeMaxDynamicSharedMemorySize, SMEM_TOTAL);

    zero_cnt_kernel<<<SCANB, 256>>>((const int*)eidx);   // also detects dtype
    hist_kernel<<<NE / 256, 256>>>(eidx);
    scan1_kernel<<<SCANB, 256>>>();
    scan2_kernel<<<1, 512>>>();
    addback_kernel<<<SCANB, 256>>>();
    fill_kernel<<<NE / 256, 256>>>(eidx);
    gather_kernel<<<NV / 8, 256>>>(efeat);
    prep_weights_kernel<<<dim3(64, 16), 256>>>(W1, W2, W3);
    mlp_mma_kernel<<<(NV + 127) / 128, 512, SMEM_TOTAL>>>(vfeat, b1, b2, b3, out);
}